// round 12
// baseline (speedup 1.0000x reference)
#include <cuda_runtime.h>
#include <cuda_fp16.h>
#include <cuda_bf16.h>
#include <cstdint>

#define N_NODESC 100000
#define N_EDGESC 1600000
#define N_GRAPHS 2048
#define VOCABC   1000
#define HID      64
#define N_CL     2
#define SCAN_B   1024
#define NB_N     ((N_NODESC + SCAN_B - 1) / SCAN_B)   // 98
#define NB_G     ((N_GRAPHS + SCAN_B - 1) / SCAN_B)   // 2
#define VB       ((VOCABC + 7) / 8)                   // vocab blocks (8 rows/block)

// ---------------- scratch (device globals; referenced ONLY from device code) -
__device__ int            g_degi[N_NODESC];
__device__ int            g_incl[N_NODESC];    // inclusive scan of deg (CSR row ends)
__device__ int            g_cursor[N_NODESC];  // exclusive prefix (read-only in fill)
__device__ unsigned short g_rank[N_EDGESC];    // edge rank within its target group
__device__ int            g_gcnt[N_GRAPHS];
__device__ int            g_gincl[N_GRAPHS];
__device__ int            g_bsum[NB_N + NB_G];
__device__ int            g_arrive;
__device__ float          g_dinv[N_NODESC];
__device__ int            g_csr[N_EDGESC];     // source node per CSR slot
__device__ unsigned int   g_px[N_NODESC];      // packed (x:u16 | dinv:fp16<<16)
__device__ __half         g_tvh[VOCABC * HID]; // emb @ W1, fp16 (128 KB, L1-resident)
__device__ __half         g_ts2[(size_t)N_NODESC * HID];  // layer-2 messages (fp16)
__device__ float          g_sums[(size_t)N_GRAPHS * HID]; // pooled sums

// ---------------- zero scratch ----------------------------------------------
__global__ void k_zero(int N) {
    int i = blockIdx.x * blockDim.x + threadIdx.x;
    if (i < N) g_degi[i] = 0;
    if (i < N_GRAPHS) g_gcnt[i] = 0;
    if (i < N_GRAPHS * HID) g_sums[i] = 0.f;
    if (i == 0) g_arrive = 0;
}

// ---------------- fused: counts (+edge ranks) + vocab GEMM (fp16 out) --------
__global__ void k_count_vocab(const int* __restrict__ col,
                              const int* __restrict__ batch,
                              const float* __restrict__ emb,
                              const float* __restrict__ W, int E, int N, int V) {
    __shared__ float sW[HID * HID];
    if (blockIdx.x < VB) {
        int tid = threadIdx.x;
        for (int i = tid; i < HID * HID; i += blockDim.x) sW[i] = W[i];
        __syncthreads();
        int lane = tid & 31, warp = tid >> 5;
        int r = blockIdx.x * 8 + warp;
        if (r >= V) return;
        const float* e = emb + (size_t)r * HID;
        float e_lo = e[lane], e_hi = e[lane + 32];
        // lane owns columns 2*lane, 2*lane+1
        float a0 = 0.f, a1 = 0.f;
        #pragma unroll
        for (int k = 0; k < 32; k++) {
            float ek = __shfl_sync(0xffffffffu, e_lo, k);
            a0 = fmaf(ek, sW[k * HID + 2 * lane],     a0);
            a1 = fmaf(ek, sW[k * HID + 2 * lane + 1], a1);
        }
        #pragma unroll
        for (int k = 0; k < 32; k++) {
            float ek = __shfl_sync(0xffffffffu, e_hi, k);
            a0 = fmaf(ek, sW[(k + 32) * HID + 2 * lane],     a0);
            a1 = fmaf(ek, sW[(k + 32) * HID + 2 * lane + 1], a1);
        }
        reinterpret_cast<__half2*>(g_tvh)[(size_t)r * 32 + lane] =
            __floats2half2_rn(a0, a1);
    } else {
        int i = (blockIdx.x - VB) * blockDim.x + threadIdx.x;
        if (i < E) {
            int r = atomicAdd(&g_degi[col[i]], 1);
            g_rank[i] = (unsigned short)r;
        } else if (i < E + N) {
            atomicAdd(&g_gcnt[batch[i - E]], 1);
        }
    }
}

// ---------------- one-launch dual scan (all blocks wave-1 resident) ----------
__device__ __forceinline__ int warp_incl_scan(int x, int lane) {
    #pragma unroll
    for (int o = 1; o < 32; o <<= 1) {
        int u = __shfl_up_sync(0xffffffffu, x, o);
        if (lane >= o) x += u;
    }
    return x;
}

__global__ void k_scan_all(int N) {
    __shared__ int wsum[32];
    __shared__ int spre;
    int t = threadIdx.x, lane = t & 31, w = t >> 5;
    bool isDeg = blockIdx.x < NB_N;
    int lo  = isDeg ? 0 : NB_N;
    int n   = isDeg ? N : N_GRAPHS;
    int idx = (blockIdx.x - lo) * SCAN_B + t;
    int v   = 0;
    if (idx < n) v = isDeg ? g_degi[idx] : g_gcnt[idx];

    int incl = warp_incl_scan(v, lane);
    if (lane == 31) wsum[w] = incl;
    __syncthreads();
    if (w == 0) wsum[lane] = warp_incl_scan(wsum[lane], lane);
    __syncthreads();
    int blockIncl = incl + (w > 0 ? wsum[w - 1] : 0);
    int blockTot = wsum[31];

    if (t == 0) {
        g_bsum[blockIdx.x] = blockTot;
        __threadfence();
        atomicAdd(&g_arrive, 1);
        while (atomicAdd(&g_arrive, 0) < (int)gridDim.x) { }
    }
    __syncthreads();

    if (w == 0) {
        int pre = 0;
        for (int j = lo + lane; j < (int)blockIdx.x; j += 32) pre += g_bsum[j];
        #pragma unroll
        for (int o = 16; o > 0; o >>= 1) pre += __shfl_down_sync(0xffffffffu, pre, o);
        if (lane == 0) spre = pre;
    }
    __syncthreads();
    int fin = blockIncl + spre;

    if (idx < n) {
        if (isDeg) {
            g_incl[idx]   = fin;
            g_cursor[idx] = fin - v;                 // exclusive prefix
            g_dinv[idx]   = rsqrtf((float)(v + 1));  // +1 self loop
        } else {
            g_gincl[idx] = fin;
        }
    }
}

// ---------------- fused: CSR fill (rank-based) + packed (x,dinv) build -------
__global__ void k_fill(const int* __restrict__ row,
                       const int* __restrict__ col,
                       const int* __restrict__ x, int E, int N) {
    int i = blockIdx.x * blockDim.x + threadIdx.x;
    if (i < E) {
        int c = col[i];
        int slot = g_cursor[c] + (int)g_rank[i];
        g_csr[slot] = row[i];
    } else {
        int node = i - E;
        if (node >= N) return;
        unsigned int xv = (unsigned int)x[node] & 0xFFFFu;
        unsigned short dh = __half_as_ushort(__float2half_rn(g_dinv[node]));
        g_px[node] = xv | ((unsigned int)dh << 16);
    }
}

// ---------------- layer-1 gather via packed vocab lookup ---------------------
// acc = d_c*tv[x_c] + sum_r d_r*tv[x_r]; tv rows served from L1 (128 KB table)
__device__ __forceinline__ float2 l1_gather(const __half2* __restrict__ tv,
                                            int c, int lane) {
    unsigned int pc = __ldg(&g_px[c]);
    float2 acc;
    {
        float dd = __half2float(__ushort_as_half((unsigned short)(pc >> 16)));
        float2 f = __half22float2(__ldg(&tv[(size_t)(pc & 0xFFFFu) * 32 + lane]));
        acc.x = dd * f.x;
        acc.y = dd * f.y;
    }
    int start = (c == 0) ? 0 : g_incl[c - 1];
    int end = g_incl[c];
    int e = start;
    while (e + 8 <= end) {
        int r[8];
        #pragma unroll
        for (int j = 0; j < 8; j++) r[j] = g_csr[e + j];
        unsigned int pk[8];
        #pragma unroll
        for (int j = 0; j < 8; j++) pk[j] = __ldg(&g_px[r[j]]);
        float2 v[8];
        #pragma unroll
        for (int j = 0; j < 8; j++)
            v[j] = __half22float2(__ldg(&tv[(size_t)(pk[j] & 0xFFFFu) * 32 + lane]));
        #pragma unroll
        for (int j = 0; j < 8; j++) {
            float dd = __half2float(__ushort_as_half((unsigned short)(pk[j] >> 16)));
            acc.x = fmaf(dd, v[j].x, acc.x);
            acc.y = fmaf(dd, v[j].y, acc.y);
        }
        e += 8;
    }
    for (; e < end; e++) {
        int r = g_csr[e];
        unsigned int pk = __ldg(&g_px[r]);
        float dd = __half2float(__ushort_as_half((unsigned short)(pk >> 16)));
        float2 f = __half22float2(__ldg(&tv[(size_t)(pk & 0xFFFFu) * 32 + lane]));
        acc.x = fmaf(dd, f.x, acc.x);
        acc.y = fmaf(dd, f.y, acc.y);
    }
    return acc;
}

// ---------------- fused: layer-1 gather + ReLU + GEMM(W2) -> ts2 (fp16) ------
__global__ void k_gather_mm(const float* __restrict__ b1,
                            const float* __restrict__ W2, int n) {
    __shared__ float  sW[HID * HID];
    __shared__ float4 se[8][32];      // per-warp duplicated-e buffer
    int tid = threadIdx.x;
    for (int i = tid; i < HID * HID; i += blockDim.x) sW[i] = W2[i];
    __syncthreads();
    int lane = tid & 31, warp = tid >> 5, wpb = blockDim.x >> 5;
    float2 bb = reinterpret_cast<const float2*>(b1)[lane];
    const __half2* tv = reinterpret_cast<const __half2*>(g_tvh);
    const unsigned long long* wu = reinterpret_cast<const unsigned long long*>(sW);
    const ulonglong2* eu = reinterpret_cast<const ulonglong2*>(&se[warp][0]);
    for (int c = blockIdx.x * wpb + warp; c < n; c += gridDim.x * wpb) {
        float2 s = l1_gather(tv, c, lane);
        float d = g_dinv[c];
        float ex = fmaxf(fmaf(d, s.x, bb.x), 0.f);   // relu(h), col 2*lane
        float ey = fmaxf(fmaf(d, s.y, bb.y), 0.f);   // col 2*lane+1
        __syncwarp();
        se[warp][lane] = make_float4(ex, ex, ey, ey);
        __syncwarp();
        unsigned long long acc = 0ull;               // packed (0.f, 0.f)
        #pragma unroll
        for (int k = 0; k < HID; k += 2) {
            ulonglong2 ee = eu[k >> 1];              // dup(e_k), dup(e_{k+1})
            unsigned long long w0 = wu[k * 32 + lane];
            unsigned long long w1 = wu[(k + 1) * 32 + lane];
            asm("fma.rn.f32x2 %0, %1, %2, %0;" : "+l"(acc) : "l"(ee.x), "l"(w0));
            asm("fma.rn.f32x2 %0, %1, %2, %0;" : "+l"(acc) : "l"(ee.y), "l"(w1));
        }
        float a, bc;
        asm("mov.b64 {%0, %1}, %2;" : "=f"(a), "=f"(bc) : "l"(acc));
        reinterpret_cast<__half2*>(g_ts2)[(size_t)c * 32 + lane] =
            __floats2half2_rn(a * d, bc * d);
    }
}

// ---------------- warp CSR gather over fp16 messages (layer 2) ---------------
__device__ __forceinline__ float2 csr_gather(const __half2* __restrict__ ts,
                                             int c, int lane) {
    int start = (c == 0) ? 0 : g_incl[c - 1];
    int end = g_incl[c];
    float2 a0 = __half22float2(ts[(size_t)c * 32 + lane]);
    float2 a1 = make_float2(0.f, 0.f);
    int e = start;
    while (e + 8 <= end) {
        int r[8];
        #pragma unroll
        for (int j = 0; j < 8; j++) r[j] = g_csr[e + j];
        float2 v[8];
        #pragma unroll
        for (int j = 0; j < 8; j++) v[j] = __half22float2(ts[(size_t)r[j] * 32 + lane]);
        #pragma unroll
        for (int j = 0; j < 8; j += 2) {
            a0.x += v[j].x;     a0.y += v[j].y;
            a1.x += v[j + 1].x; a1.y += v[j + 1].y;
        }
        e += 8;
    }
    for (; e < end; e++) {
        int r = g_csr[e];
        float2 v = __half22float2(ts[(size_t)r * 32 + lane]);
        a0.x += v.x; a0.y += v.y;
    }
    a0.x += a1.x;
    a0.y += a1.y;
    return a0;
}

// ---------------- fused: layer-2 gather + ReLU + pool scatter (persistent) ---
__global__ void k_gather_pool(const int* __restrict__ batch,
                              const float* __restrict__ b2, int n) {
    int lane = threadIdx.x & 31;
    int warp = threadIdx.x >> 5;
    int wpb = blockDim.x >> 5;
    const __half2* ts = reinterpret_cast<const __half2*>(g_ts2);
    for (int c = blockIdx.x * wpb + warp; c < n; c += gridDim.x * wpb) {
        float2 s = csr_gather(ts, c, lane);
        float d = g_dinv[c];
        float2 bb = reinterpret_cast<const float2*>(b2)[lane];
        float hx = fmaxf(fmaf(d, s.x, bb.x), 0.f);
        float hy = fmaxf(fmaf(d, s.y, bb.y), 0.f);
        int g = batch[c];
        float* dst = g_sums + (size_t)g * HID + 2 * lane;
        asm volatile("red.global.add.v2.f32 [%0], {%1,%2};"
                     :: "l"(dst), "f"(hx), "f"(hy) : "memory");
    }
}

// ---------------- head: out[g] = (sums[g]/cnt) @ Wl + bl ---------------------
__global__ void k_head(const float* __restrict__ Wl,
                       const float* __restrict__ bl,
                       float* __restrict__ out) {
    int lane = threadIdx.x & 31;
    int warp = threadIdx.x >> 5;
    int g = blockIdx.x * (blockDim.x >> 5) + warp;
    if (g >= N_GRAPHS) return;
    int start = (g == 0) ? 0 : g_gincl[g - 1];
    int cnt = g_gincl[g] - start;
    float inv = 1.0f / fmaxf((float)cnt, 1.0f);
    float s0 = g_sums[(size_t)g * HID + 2 * lane] * inv;
    float s1 = g_sums[(size_t)g * HID + 2 * lane + 1] * inv;
    float a0 = s0 * Wl[(2 * lane) * N_CL + 0] + s1 * Wl[(2 * lane + 1) * N_CL + 0];
    float a1 = s0 * Wl[(2 * lane) * N_CL + 1] + s1 * Wl[(2 * lane + 1) * N_CL + 1];
    #pragma unroll
    for (int off = 16; off > 0; off >>= 1) {
        a0 += __shfl_down_sync(0xffffffffu, a0, off);
        a1 += __shfl_down_sync(0xffffffffu, a1, off);
    }
    if (lane == 0) {
        out[g * N_CL + 0] = a0 + bl[0];
        out[g * N_CL + 1] = a1 + bl[1];
    }
}

// ---------------- launch ----------------------------------------------------
extern "C" void kernel_launch(void* const* d_in, const int* in_sizes, int n_in,
                              void* d_out, int out_size) {
    const int*   x     = (const int*)  d_in[0];
    const int*   eidx  = (const int*)  d_in[1];
    const int*   batch = (const int*)  d_in[2];
    const float* emb   = (const float*)d_in[3];
    const float* W1    = (const float*)d_in[4];
    const float* b1    = (const float*)d_in[5];
    const float* W2    = (const float*)d_in[6];
    const float* b2    = (const float*)d_in[7];
    const float* Wl    = (const float*)d_in[8];
    const float* bl    = (const float*)d_in[9];
    float* out = (float*)d_out;

    const int N = in_sizes[0];
    const int E = in_sizes[1] / 2;
    const int V = in_sizes[3] / HID;
    const int* row = eidx;       // sources
    const int* col = eidx + E;   // targets

    const int T = 256;
    const int ZB = (N_GRAPHS * HID + T - 1) / T;   // covers degi/gcnt/sums
    const int CB = (E + N + T - 1) / T;            // count work

    // zero -> fused count+vocab GEMM -> dual scan -> CSR fill + px build
    k_zero       <<<ZB, T>>>(N);
    k_count_vocab<<<VB + CB, T>>>(col, batch, emb, W1, E, N, V);
    k_scan_all   <<<NB_N + NB_G, SCAN_B>>>(N);
    k_fill       <<<(E + N + T - 1) / T, T>>>(row, col, x, E, N);

    // layer 1 gather (vocab-table) + GEMM(W2) fused -> ts2 (persistent wave)
    k_gather_mm<<<1184, 256>>>(b1, W2, N);

    // layer 2 gather + pool scatter fused (persistent)
    k_gather_pool<<<1184, 256>>>(batch, b2, N);

    // head
    k_head<<<(N_GRAPHS + 7) / 8, 256>>>(Wl, bl, out);
}